// round 1
// baseline (speedup 1.0000x reference)
#include <cuda_runtime.h>
#include <cuda_bf16.h>

// ---------------------------------------------------------------------------
// ResidualGatedGCN fused pipeline (fp32 baseline)
//   proj  = nf @ W + b          -> g_proj [50000,512]  (h|Q|K|V)
//   ep    = ef @ We + be        -> g_ep   [600000,128]
//   out   = h                   (init)
//   out[r] += sigmoid(Q[r]+K[s]+ep[e]) * V[s]   (atomic scatter)
// ---------------------------------------------------------------------------

#define N_NODES 50000
#define N_EDGES 600000
#define EMBED   128

__device__ float g_proj[(size_t)N_NODES * 512];     // 102.4 MB
__device__ float g_ep  [(size_t)N_EDGES * EMBED];   // 307.2 MB

// ---------------------------------------------------------------------------
// SGEMM: C[M,N] = A[M,K] @ B[K,N] + bias[N]
// BM=64, BN=64, BK=16, 256 threads, 4x4 register tile per thread.
// ---------------------------------------------------------------------------
#define BM 64
#define BN 64
#define BK 16

__global__ __launch_bounds__(256, 2)
void sgemm_bias_kernel(const float* __restrict__ A,
                       const float* __restrict__ B,
                       const float* __restrict__ bias,
                       float* __restrict__ C,
                       int M, int N, int K)
{
    __shared__ float As[BK][BM + 4];   // transposed A tile, padded vs STS conflicts
    __shared__ float Bs[BK][BN];

    const int tid  = threadIdx.x;
    const int row0 = blockIdx.y * BM;
    const int col0 = blockIdx.x * BN;

    const int tr = tid / 16;          // 0..15 (M direction)
    const int tc = tid % 16;          // 0..15 (N direction)

    // A tile load mapping: 64 rows x 16 cols, one float4 per thread along K
    const int a_r = tid / 4;          // 0..63
    const int a_c = (tid % 4) * 4;    // 0,4,8,12
    // B tile load mapping: 16 rows x 64 cols, one float4 per thread along N
    const int b_r = tid / 16;         // 0..15
    const int b_c = (tid % 16) * 4;   // 0..60

    float acc[4][4] = {};

    for (int kt = 0; kt < K; kt += BK) {
        // ---- load A tile (guard rows) ----
        float4 av = make_float4(0.f, 0.f, 0.f, 0.f);
        const int gr = row0 + a_r;
        if (gr < M) av = *(const float4*)&A[(size_t)gr * K + kt + a_c];
        As[a_c + 0][a_r] = av.x;
        As[a_c + 1][a_r] = av.y;
        As[a_c + 2][a_r] = av.z;
        As[a_c + 3][a_r] = av.w;

        // ---- load B tile (K and N always divisible here) ----
        float4 bv = *(const float4*)&B[(size_t)(kt + b_r) * N + col0 + b_c];
        *(float4*)&Bs[b_r][b_c] = bv;

        __syncthreads();

        #pragma unroll
        for (int k = 0; k < BK; k++) {
            float4 a = *(const float4*)&As[k][tr * 4];
            float4 b = *(const float4*)&Bs[k][tc * 4];
            acc[0][0] += a.x * b.x; acc[0][1] += a.x * b.y; acc[0][2] += a.x * b.z; acc[0][3] += a.x * b.w;
            acc[1][0] += a.y * b.x; acc[1][1] += a.y * b.y; acc[1][2] += a.y * b.z; acc[1][3] += a.y * b.w;
            acc[2][0] += a.z * b.x; acc[2][1] += a.z * b.y; acc[2][2] += a.z * b.z; acc[2][3] += a.z * b.w;
            acc[3][0] += a.w * b.x; acc[3][1] += a.w * b.y; acc[3][2] += a.w * b.z; acc[3][3] += a.w * b.w;
        }
        __syncthreads();
    }

    // ---- epilogue: bias + store ----
    const int c = col0 + tc * 4;
    const float4 bsv = *(const float4*)&bias[c];
    #pragma unroll
    for (int i = 0; i < 4; i++) {
        const int r = row0 + tr * 4 + i;
        if (r < M) {
            float4 o;
            o.x = acc[i][0] + bsv.x;
            o.y = acc[i][1] + bsv.y;
            o.z = acc[i][2] + bsv.z;
            o.w = acc[i][3] + bsv.w;
            *(float4*)&C[(size_t)r * N + c] = o;
        }
    }
}

// ---------------------------------------------------------------------------
// out[n,:] = h[n,:] = g_proj[n, 0:128]
// ---------------------------------------------------------------------------
__global__ void init_out_kernel(float* __restrict__ out)
{
    int i = blockIdx.x * blockDim.x + threadIdx.x;   // over N_NODES*32 float4s
    if (i < N_NODES * 32) {
        int row = i >> 5;
        int c4  = i & 31;
        float4 v = *(const float4*)&g_proj[(size_t)row * 512 + c4 * 4];
        ((float4*)out)[i] = v;
    }
}

// ---------------------------------------------------------------------------
// Per-edge: eta = sigmoid(Q[r] + K[s] + ep[e]); out[r] += eta * V[s]
// One warp per edge; float4 per lane (32 lanes * 4 = 128 dims).
// ---------------------------------------------------------------------------
__device__ __forceinline__ float sigmoidf_(float x) {
    return 1.0f / (1.0f + expf(-x));
}

__global__ __launch_bounds__(256)
void edge_scatter_kernel(const int* __restrict__ senders,
                         const int* __restrict__ receivers,
                         float* __restrict__ out)
{
    const int warp = (blockIdx.x * blockDim.x + threadIdx.x) >> 5;
    const int lane = threadIdx.x & 31;
    if (warp >= N_EDGES) return;
    const int e = warp;

    const int s = __ldg(&senders[e]);
    const int r = __ldg(&receivers[e]);
    const int d = lane * 4;

    const float4 ep = *(const float4*)&g_ep  [(size_t)e * 128 + d];
    const float4 q  = *(const float4*)&g_proj[(size_t)r * 512 + 128 + d];
    const float4 kk = *(const float4*)&g_proj[(size_t)s * 512 + 256 + d];
    const float4 v  = *(const float4*)&g_proj[(size_t)s * 512 + 384 + d];

    float4 m;
    m.x = sigmoidf_(q.x + kk.x + ep.x) * v.x;
    m.y = sigmoidf_(q.y + kk.y + ep.y) * v.y;
    m.z = sigmoidf_(q.z + kk.z + ep.z) * v.z;
    m.w = sigmoidf_(q.w + kk.w + ep.w) * v.w;

    float* o = &out[(size_t)r * 128 + d];
    atomicAdd(o + 0, m.x);
    atomicAdd(o + 1, m.y);
    atomicAdd(o + 2, m.z);
    atomicAdd(o + 3, m.w);
}

// ---------------------------------------------------------------------------
// Launch
// Inputs (metadata order):
//  0 node_features [50000,128] f32
//  1 senders       [600000]    i32
//  2 receivers     [600000]    i32
//  3 edge_features [600000,128] f32
//  4 W_kernel      [128,512]   f32
//  5 W_bias        [512]       f32
//  6 We_kernel     [128,128]   f32
//  7 We_bias       [128]       f32
// Output: [50000,128] f32
// ---------------------------------------------------------------------------
extern "C" void kernel_launch(void* const* d_in, const int* in_sizes, int n_in,
                              void* d_out, int out_size)
{
    const float* nf   = (const float*)d_in[0];
    const int*   snd  = (const int*)  d_in[1];
    const int*   rcv  = (const int*)  d_in[2];
    const float* ef   = (const float*)d_in[3];
    const float* Wk   = (const float*)d_in[4];
    const float* Wb   = (const float*)d_in[5];
    const float* Wek  = (const float*)d_in[6];
    const float* Web  = (const float*)d_in[7];
    float* out = (float*)d_out;

    float* proj_ptr;
    float* ep_ptr;
    cudaGetSymbolAddress((void**)&proj_ptr, g_proj);
    cudaGetSymbolAddress((void**)&ep_ptr,   g_ep);

    // 1) node projection: [50000,512]
    {
        dim3 grid(512 / BN, (N_NODES + BM - 1) / BM);
        sgemm_bias_kernel<<<grid, 256>>>(nf, Wk, Wb, proj_ptr, N_NODES, 512, EMBED);
    }
    // 2) edge projection: [600000,128]
    {
        dim3 grid(EMBED / BN, N_EDGES / BM);
        sgemm_bias_kernel<<<grid, 256>>>(ef, Wek, Web, ep_ptr, N_EDGES, EMBED, EMBED);
    }
    // 3) out = h
    {
        int total = N_NODES * 32;
        init_out_kernel<<<(total + 255) / 256, 256>>>(out);
    }
    // 4) gated message scatter
    {
        int warps_needed = N_EDGES;                 // 1 warp per edge
        int blocks = (warps_needed * 32 + 255) / 256;
        edge_scatter_kernel<<<blocks, 256>>>(snd, rcv, out);
    }
}